// round 15
// baseline (speedup 1.0000x reference)
#include <cuda_runtime.h>
#include <cuda_fp16.h>
#include <mma.h>

using namespace nvcuda;

#define N_NODES 50000
#define N_EDGES 800000
#define HIDDEN 64
#define OUT_DIM 16
#define NBLK 592          // 4 blocks/SM x 148 SMs
#define TPB 256
#define GSTRIDE (NBLK * TPB)
#define CHUNK 85          // ceil(50000/592)
#define TILE_N 64
#define NTILES 782        // ceil(50000/64)
#define AROW 136          // sA row stride in halves (128 + 8 pad)
#define CROW 68           // sC row stride in floats (64 + 4 pad)

// ---------------- device scratch ----------------
__device__ int g_count[N_NODES];
__device__ int g_off[N_NODES + 1];
__device__ int g_csr[N_EDGES];
__device__ int g_blocksum[NBLK];
__device__ int g_blockoff[NBLK];
__device__ unsigned g_bar_cnt;
__device__ unsigned g_bar_gen;
__device__ __align__(16) __half g_hx[N_NODES * HIDDEN];
__device__ __align__(16) __half g_h0[N_NODES * HIDDEN];
__device__ __align__(16) __half g_h1[N_NODES * HIDDEN];
__device__ __align__(16) __half g_wh[3 * 128 * 64];   // fp16 [layer][k][f]; k<64 Wl, k>=64 Wr

// ---------------- software grid barrier ----------------
__device__ __forceinline__ void grid_barrier() {
    __syncthreads();
    if (threadIdx.x == 0) {
        unsigned gen = *((volatile unsigned*)&g_bar_gen);
        __threadfence();
        unsigned a = atomicAdd(&g_bar_cnt, 1u);
        if (a == NBLK - 1) {
            g_bar_cnt = 0;
            __threadfence();
            atomicExch(&g_bar_gen, gen + 1u);
        } else {
            while (*((volatile unsigned*)&g_bar_gen) == gen) { __nanosleep(32); }
        }
        __threadfence();
    }
    __syncthreads();
}

__device__ __forceinline__ float4 fma4(float s, float4 w, float4 acc) {
    acc.x = fmaf(s, w.x, acc.x);
    acc.y = fmaf(s, w.y, acc.y);
    acc.z = fmaf(s, w.z, acc.z);
    acc.w = fmaf(s, w.w, acc.w);
    return acc;
}
__device__ __forceinline__ void acc_h8(float4& lo, float4& hi, uint4 v) {
    __half2* h = (__half2*)&v;
    float2 f0 = __half22float2(h[0]);
    float2 f1 = __half22float2(h[1]);
    float2 f2 = __half22float2(h[2]);
    float2 f3 = __half22float2(h[3]);
    lo.x += f0.x; lo.y += f0.y; lo.z += f1.x; lo.w += f1.y;
    hi.x += f2.x; hi.y += f2.y; hi.z += f3.x; hi.w += f3.y;
}
__device__ __forceinline__ uint2 f4_to_h4(float4 a) {
    __half2 lo = __floats2half2_rn(a.x, a.y);
    __half2 hi = __floats2half2_rn(a.z, a.w);
    uint2 r;
    r.x = *(unsigned*)&lo;
    r.y = *(unsigned*)&hi;
    return r;
}

// ---------------- one 64-node tile: shuffle-fed fp16 gather -> wmma -> epilogue ----------------
template <bool FINAL>
__device__ __forceinline__ void layer_tile(
    const __half* __restrict__ xin,
    const __half* __restrict__ whL,  // fp16 [128][64]
    const float* __restrict__ Wog,   // [64][16] (FINAL)
    const float* __restrict__ bl,
    const float* __restrict__ bout,
    void* __restrict__ dst,
    int tile, int tid, __half* sA, float* sC) {
    int node0 = tile * TILE_N;
    // ---- gather: 8 threads/node, shuffle-distributed coalesced indices ----
    {
        int ln = tid >> 3, q = tid & 7;
        int lane = tid & 31;
        int lb = lane & ~7;                      // group's base lane in warp
        unsigned gmask = 0xFFu << lb;            // this 8-lane group
        const uint4* x8 = (const uint4*)xin;
#pragma unroll
        for (int sub = 0; sub < 2; sub++) {
            int n = sub * 32 + ln;
            int node = node0 + n;
            float4 aLo = make_float4(0.f, 0.f, 0.f, 0.f);
            float4 aHi = aLo;
            uint4 xv = make_uint4(0u, 0u, 0u, 0u);
            if (node < N_NODES) {
                int s = __ldg(&g_off[node]);
                int e = __ldg(&g_off[node + 1]);
                int nch = (e - s) >> 3;          // full 8-edge chunks
                int i = s;
                int idx0 = (nch > 0) ? __ldg(&g_csr[i + q]) : 0;
                int idx1 = (nch > 1) ? __ldg(&g_csr[i + 8 + q]) : 0;
                for (int c = 0; c < nch; c++) {
                    int cur = idx0;
                    idx0 = idx1;
                    idx1 = (c + 2 < nch) ? __ldg(&g_csr[i + 16 + q]) : 0;
                    int s0 = __shfl_sync(gmask, cur, lb + 0);
                    int s1 = __shfl_sync(gmask, cur, lb + 1);
                    int s2 = __shfl_sync(gmask, cur, lb + 2);
                    int s3 = __shfl_sync(gmask, cur, lb + 3);
                    int s4 = __shfl_sync(gmask, cur, lb + 4);
                    int s5 = __shfl_sync(gmask, cur, lb + 5);
                    int s6 = __shfl_sync(gmask, cur, lb + 6);
                    int s7 = __shfl_sync(gmask, cur, lb + 7);
                    uint4 v0 = __ldg(&x8[s0 * 8 + q]);
                    uint4 v1 = __ldg(&x8[s1 * 8 + q]);
                    uint4 v2 = __ldg(&x8[s2 * 8 + q]);
                    uint4 v3 = __ldg(&x8[s3 * 8 + q]);
                    uint4 v4 = __ldg(&x8[s4 * 8 + q]);
                    uint4 v5 = __ldg(&x8[s5 * 8 + q]);
                    uint4 v6 = __ldg(&x8[s6 * 8 + q]);
                    uint4 v7 = __ldg(&x8[s7 * 8 + q]);
                    acc_h8(aLo, aHi, v0); acc_h8(aLo, aHi, v1);
                    acc_h8(aLo, aHi, v2); acc_h8(aLo, aHi, v3);
                    acc_h8(aLo, aHi, v4); acc_h8(aLo, aHi, v5);
                    acc_h8(aLo, aHi, v6); acc_h8(aLo, aHi, v7);
                    i += 8;
                }
                int rem = e - i;
                if (rem > 0) {
                    int cur = (i + q < e) ? __ldg(&g_csr[i + q]) : 0;
                    for (int j = 0; j < rem; j++) {
                        int src = __shfl_sync(gmask, cur, lb + j);
                        uint4 v = __ldg(&x8[src * 8 + q]);
                        acc_h8(aLo, aHi, v);
                    }
                }
                int deg = e - s;
                float invd = 1.0f / (float)(deg > 0 ? deg : 1);
                aLo.x *= invd; aLo.y *= invd; aLo.z *= invd; aLo.w *= invd;
                aHi.x *= invd; aHi.y *= invd; aHi.z *= invd; aHi.w *= invd;
                xv = __ldg(&x8[node * 8 + q]);
            }
            uint2 hLo = f4_to_h4(aLo);
            uint2 hHi = f4_to_h4(aHi);
            *(uint4*)&sA[n * AROW + q * 8] = make_uint4(hLo.x, hLo.y, hHi.x, hHi.y);
            *(uint4*)&sA[n * AROW + 64 + q * 8] = xv;
        }
    }
    __syncthreads();

    // ---- wmma GEMM: C[64][64] = sA[64][128] @ whL[128][64], fp32 accumulate ----
    {
        int wid = tid >> 5;
        int rowblk = wid >> 1;
        int colblk0 = (wid & 1) * 2;
        wmma::fragment<wmma::accumulator, 16, 16, 16, float> c0, c1;
        wmma::fill_fragment(c0, 0.0f);
        wmma::fill_fragment(c1, 0.0f);
#pragma unroll
        for (int k = 0; k < 8; k++) {
            wmma::fragment<wmma::matrix_a, 16, 16, 16, __half, wmma::row_major> af;
            wmma::load_matrix_sync(af, sA + rowblk * 16 * AROW + k * 16, AROW);
            wmma::fragment<wmma::matrix_b, 16, 16, 16, __half, wmma::row_major> b0, b1;
            wmma::load_matrix_sync(b0, whL + k * 16 * 64 + colblk0 * 16, 64);
            wmma::load_matrix_sync(b1, whL + k * 16 * 64 + (colblk0 + 1) * 16, 64);
            wmma::mma_sync(c0, af, b0, c0);
            wmma::mma_sync(c1, af, b1, c1);
        }
        wmma::store_matrix_sync(sC + rowblk * 16 * CROW + colblk0 * 16, c0, CROW,
                                wmma::mem_row_major);
        wmma::store_matrix_sync(sC + rowblk * 16 * CROW + (colblk0 + 1) * 16, c1, CROW,
                                wmma::mem_row_major);
    }
    __syncthreads();

    // ---- epilogue: bias + relu ----
    int n = tid >> 2;
    int f0 = (tid & 3) * 16;
    float4 y[4];
    {
        const float* cr = &sC[n * CROW + f0];
#pragma unroll
        for (int j = 0; j < 4; j++) {
            float4 v = *(const float4*)&cr[j * 4];
            float4 bb;
            bb.x = __ldg(&bl[f0 + j * 4]);     bb.y = __ldg(&bl[f0 + j * 4 + 1]);
            bb.z = __ldg(&bl[f0 + j * 4 + 2]); bb.w = __ldg(&bl[f0 + j * 4 + 3]);
            v.x = fmaxf(v.x + bb.x, 0.f); v.y = fmaxf(v.y + bb.y, 0.f);
            v.z = fmaxf(v.z + bb.z, 0.f); v.w = fmaxf(v.w + bb.w, 0.f);
            y[j] = v;
        }
    }
    int gn = node0 + n;
    if (!FINAL) {
        if (gn < N_NODES) {
            __half* dh = (__half*)dst;
            uint2 h0 = f4_to_h4(y[0]);
            uint2 h1 = f4_to_h4(y[1]);
            uint2 h2 = f4_to_h4(y[2]);
            uint2 h3 = f4_to_h4(y[3]);
            *(uint4*)&dh[gn * 64 + f0] = make_uint4(h0.x, h0.y, h1.x, h1.y);
            *(uint4*)&dh[gn * 64 + f0 + 8] = make_uint4(h2.x, h2.y, h3.x, h3.y);
        }
        __syncthreads();
    } else {
        float* cr = &sC[n * CROW + f0];
#pragma unroll
        for (int j = 0; j < 4; j++) *(float4*)&cr[j * 4] = y[j];
        __syncthreads();
        int n2 = tid >> 2;
        int o0 = (tid & 3) * 4;
        float4 oacc;
        oacc.x = __ldg(&bout[o0]); oacc.y = __ldg(&bout[o0 + 1]);
        oacc.z = __ldg(&bout[o0 + 2]); oacc.w = __ldg(&bout[o0 + 3]);
        const float* yr = &sC[n2 * CROW];
#pragma unroll 4
        for (int k4 = 0; k4 < 16; k4++) {
            float4 yv = *(const float4*)&yr[k4 * 4];
            const float* wb = &Wog[k4 * 64 + o0];
            float4 w0 = __ldg((const float4*)&wb[0]);
            float4 w1 = __ldg((const float4*)&wb[16]);
            float4 w2 = __ldg((const float4*)&wb[32]);
            float4 w3 = __ldg((const float4*)&wb[48]);
            oacc = fma4(yv.x, w0, oacc); oacc = fma4(yv.y, w1, oacc);
            oacc = fma4(yv.z, w2, oacc); oacc = fma4(yv.w, w3, oacc);
        }
        int gn2 = node0 + n2;
        if (gn2 < N_NODES) *(float4*)&((float*)dst)[gn2 * OUT_DIM + o0] = oacc;
        __syncthreads();
    }
}

// ---------------- persistent kernel ----------------
__global__ void __launch_bounds__(TPB, 4) fused_kernel(
    const float* __restrict__ x, const int* __restrict__ ei,
    const float* __restrict__ Wl, const float* __restrict__ bl,
    const float* __restrict__ Wr, const float* __restrict__ Wout,
    const float* __restrict__ bout, float* __restrict__ out) {
    __shared__ __half sA[TILE_N * AROW];   // 17.0 KB
    __shared__ float sC[TILE_N * CROW];    // 17.0 KB
    __shared__ int sInts[8];

    int tid = threadIdx.x;
    int b = blockIdx.x;
    int gtid = b * TPB + tid;
    int lane = tid & 31, w = tid >> 5;

    // phase 0: zero counts + convert x and weights to fp16
    for (int i = gtid; i < N_NODES; i += GSTRIDE) g_count[i] = 0;
    {
        const float4* x4 = (const float4*)x;
        uint2* hx = (uint2*)g_hx;
        for (int i = gtid; i < N_NODES * HIDDEN / 4; i += GSTRIDE) {
            float4 v = __ldg(&x4[i]);
            hx[i] = f4_to_h4(v);
        }
        for (int i = gtid; i < 3 * 128 * 64; i += GSTRIDE) {
            int l = i / 8192;
            int r = i - l * 8192;
            int k = r >> 6;
            int f = r & 63;
            float v = (k < 64) ? __ldg(&Wl[l * 4096 + k * 64 + f])
                               : __ldg(&Wr[l * 4096 + (k - 64) * 64 + f]);
            g_wh[i] = __float2half_rn(v);
        }
    }
    grid_barrier();

    // phase 1: histogram
    {
        const int4* dst4 = (const int4*)(ei + N_EDGES);
        for (int t = gtid; t < N_EDGES / 4; t += GSTRIDE) {
            int4 d = __ldg(&dst4[t]);
            atomicAdd(&g_count[d.x], 1);
            atomicAdd(&g_count[d.y], 1);
            atomicAdd(&g_count[d.z], 1);
            atomicAdd(&g_count[d.w], 1);
        }
    }
    grid_barrier();

    // phase 2a: block-local exclusive scan of CHUNK counts
    {
        int base = b * CHUNK;
        int idx = base + tid;
        int v = (tid < CHUNK && idx < N_NODES) ? g_count[idx] : 0;
        int s = v;
#pragma unroll
        for (int d = 1; d < 32; d <<= 1) {
            int tv = __shfl_up_sync(0xffffffffu, s, d);
            if (lane >= d) s += tv;
        }
        if (lane == 31) sInts[w] = s;
        __syncthreads();
        if (tid == 0) {
            int acc = 0;
#pragma unroll
            for (int k = 0; k < 8; k++) { int t2 = sInts[k]; sInts[k] = acc; acc += t2; }
        }
        __syncthreads();
        int incl = s + sInts[w];
        if (tid < CHUNK && idx < N_NODES) g_off[idx] = incl - v;
        if (tid == TPB - 1) g_blocksum[b] = incl;
    }
    grid_barrier();

    // phase 2b: block 0 scans the NBLK block sums (3 per thread)
    if (b == 0) {
        int base2 = tid * 3;
        int v0 = (base2 + 0 < NBLK) ? g_blocksum[base2 + 0] : 0;
        int v1 = (base2 + 1 < NBLK) ? g_blocksum[base2 + 1] : 0;
        int v2 = (base2 + 2 < NBLK) ? g_blocksum[base2 + 2] : 0;
        int tsum = v0 + v1 + v2;
        int s = tsum;
#pragma unroll
        for (int d = 1; d < 32; d <<= 1) {
            int tv = __shfl_up_sync(0xffffffffu, s, d);
            if (lane >= d) s += tv;
        }
        if (lane == 31) sInts[w] = s;
        __syncthreads();
        if (tid == 0) {
            int acc = 0;
#pragma unroll
            for (int k = 0; k < 8; k++) { int t2 = sInts[k]; sInts[k] = acc; acc += t2; }
        }
        __syncthreads();
        int excl = (s - tsum) + sInts[w];
        if (base2 + 0 < NBLK) { g_blockoff[base2 + 0] = excl; excl += v0; }
        if (base2 + 1 < NBLK) { g_blockoff[base2 + 1] = excl; excl += v1; }
        if (base2 + 2 < NBLK) { g_blockoff[base2 + 2] = excl; excl += v2; }
    }
    grid_barrier();

    // phase 2c: add block offsets; init fill cursors
    {
        int off = g_blockoff[b];
        int idx = b * CHUNK + tid;
        if (tid < CHUNK && idx < N_NODES) {
            int o = g_off[idx] + off;
            g_off[idx] = o;
            g_count[idx] = o;
        }
        if (gtid == 0) g_off[N_NODES] = N_EDGES;
    }
    grid_barrier();

    // phase 3: fill CSR
    {
        const int4* src4 = (const int4*)ei;
        const int4* dst4 = (const int4*)(ei + N_EDGES);
        for (int t = gtid; t < N_EDGES / 4; t += GSTRIDE) {
            int4 sv = __ldg(&src4[t]);
            int4 d = __ldg(&dst4[t]);
            g_csr[atomicAdd(&g_count[d.x], 1)] = sv.x;
            g_csr[atomicAdd(&g_count[d.y], 1)] = sv.y;
            g_csr[atomicAdd(&g_count[d.z], 1)] = sv.z;
            g_csr[atomicAdd(&g_count[d.w], 1)] = sv.w;
        }
    }
    grid_barrier();

    // ---- layer 1: g_hx -> g_h0 ----
    for (int tile = b; tile < NTILES; tile += NBLK)
        layer_tile<false>(g_hx, g_wh, Wout, bl, bout, g_h0, tile, tid, sA, sC);
    grid_barrier();

    // ---- layer 2: g_h0 -> g_h1 ----
    for (int tile = b; tile < NTILES; tile += NBLK)
        layer_tile<false>(g_h0, g_wh + 8192, Wout, bl + HIDDEN, bout, g_h1,
                          tile, tid, sA, sC);
    grid_barrier();

    // ---- layer 3 + output projection: g_h1 -> out ----
    for (int tile = b; tile < NTILES; tile += NBLK)
        layer_tile<true>(g_h1, g_wh + 16384, Wout, bl + 2 * HIDDEN, bout, out,
                         tile, tid, sA, sC);
}

extern "C" void kernel_launch(void* const* d_in, const int* in_sizes, int n_in,
                              void* d_out, int out_size) {
    const float* x = (const float*)d_in[0];
    const int* ei = (const int*)d_in[1];
    const float* Wl = (const float*)d_in[2];
    const float* bl = (const float*)d_in[3];
    const float* Wr = (const float*)d_in[4];
    const float* Wout = (const float*)d_in[5];
    const float* bout = (const float*)d_in[6];
    float* out = (float*)d_out;

    fused_kernel<<<NBLK, TPB>>>(x, ei, Wl, bl, Wr, Wout, bout, out);
}

// round 16
// speedup vs baseline: 1.0536x; 1.0536x over previous
#include <cuda_runtime.h>
#include <cuda_fp16.h>
#include <mma.h>

using namespace nvcuda;

#define N_NODES 50000
#define N_EDGES 800000
#define HIDDEN 64
#define OUT_DIM 16
#define NBLK 592          // 4 blocks/SM x 148 SMs
#define TPB 256
#define GSTRIDE (NBLK * TPB)
#define CHUNK 85          // ceil(50000/592)
#define TILE_N 32
#define NTILES 1563       // ceil(50000/32)
#define AROW 136          // sA row stride in halves (128 + 8 pad)
#define CROW 68           // sC row stride in floats (64 + 4 pad)

// ---------------- device scratch ----------------
__device__ int g_count[N_NODES];
__device__ int g_off[N_NODES + 1];
__device__ int g_csr[N_EDGES];
__device__ int g_blocksum[NBLK];
__device__ int g_blockoff[NBLK];
__device__ unsigned g_bar_cnt;
__device__ unsigned g_bar_gen;
__device__ __align__(16) __half g_hx[N_NODES * HIDDEN];
__device__ __align__(16) __half g_h0[N_NODES * HIDDEN];
__device__ __align__(16) __half g_h1[N_NODES * HIDDEN];
__device__ __align__(16) __half g_wh[3 * 128 * 64];   // fp16 [layer][k][f]; k<64 Wl, k>=64 Wr

// ---------------- software grid barrier ----------------
__device__ __forceinline__ void grid_barrier() {
    __syncthreads();
    if (threadIdx.x == 0) {
        unsigned gen = *((volatile unsigned*)&g_bar_gen);
        __threadfence();
        unsigned a = atomicAdd(&g_bar_cnt, 1u);
        if (a == NBLK - 1) {
            g_bar_cnt = 0;
            __threadfence();
            atomicExch(&g_bar_gen, gen + 1u);
        } else {
            while (*((volatile unsigned*)&g_bar_gen) == gen) { __nanosleep(32); }
        }
        __threadfence();
    }
    __syncthreads();
}

__device__ __forceinline__ float4 fma4(float s, float4 w, float4 acc) {
    acc.x = fmaf(s, w.x, acc.x);
    acc.y = fmaf(s, w.y, acc.y);
    acc.z = fmaf(s, w.z, acc.z);
    acc.w = fmaf(s, w.w, acc.w);
    return acc;
}
__device__ __forceinline__ void acc_h8(float4& lo, float4& hi, uint4 v) {
    __half2* h = (__half2*)&v;
    float2 f0 = __half22float2(h[0]);
    float2 f1 = __half22float2(h[1]);
    float2 f2 = __half22float2(h[2]);
    float2 f3 = __half22float2(h[3]);
    lo.x += f0.x; lo.y += f0.y; lo.z += f1.x; lo.w += f1.y;
    hi.x += f2.x; hi.y += f2.y; hi.z += f3.x; hi.w += f3.y;
}
__device__ __forceinline__ uint2 f4_to_h4(float4 a) {
    __half2 lo = __floats2half2_rn(a.x, a.y);
    __half2 hi = __floats2half2_rn(a.z, a.w);
    uint2 r;
    r.x = *(unsigned*)&lo;
    r.y = *(unsigned*)&hi;
    return r;
}

// ---------------- one 32-node tile: fp16 gather -> wmma -> epilogue ----------------
template <bool FINAL>
__device__ __forceinline__ void layer_tile(
    const __half* __restrict__ xin,
    const __half* __restrict__ whL,  // fp16 [128][64]
    const float* __restrict__ Wog,   // [64][16] (FINAL)
    const float* __restrict__ bl,
    const float* __restrict__ bout,
    void* __restrict__ dst,
    int tile, int tid, __half* sA, float* sC) {
    int node0 = tile * TILE_N;
    // ---- gather: 8 threads/node, 32 nodes, one round (R14-proven loop) ----
    {
        int ln = tid >> 3, q = tid & 7;
        const uint4* x8 = (const uint4*)xin;
        int n = ln;
        int node = node0 + n;
        float4 aLo = make_float4(0.f, 0.f, 0.f, 0.f);
        float4 aHi = aLo;
        uint4 xv = make_uint4(0u, 0u, 0u, 0u);
        if (node < N_NODES) {
            int s = __ldg(&g_off[node]);
            int e = __ldg(&g_off[node + 1]);
            int i = s;
            int i0 = 0, i1 = 0, i2 = 0, i3 = 0;
            if (i + 4 <= e) {
                i0 = __ldg(&g_csr[i]);     i1 = __ldg(&g_csr[i + 1]);
                i2 = __ldg(&g_csr[i + 2]); i3 = __ldg(&g_csr[i + 3]);
            }
            while (i + 4 <= e) {
                uint4 v0 = __ldg(&x8[i0 * 8 + q]);
                uint4 v1 = __ldg(&x8[i1 * 8 + q]);
                uint4 v2 = __ldg(&x8[i2 * 8 + q]);
                uint4 v3 = __ldg(&x8[i3 * 8 + q]);
                i += 4;
                if (i + 4 <= e) {
                    i0 = __ldg(&g_csr[i]);     i1 = __ldg(&g_csr[i + 1]);
                    i2 = __ldg(&g_csr[i + 2]); i3 = __ldg(&g_csr[i + 3]);
                }
                acc_h8(aLo, aHi, v0); acc_h8(aLo, aHi, v1);
                acc_h8(aLo, aHi, v2); acc_h8(aLo, aHi, v3);
            }
            for (; i < e; i++) {
                int s0 = __ldg(&g_csr[i]);
                uint4 v = __ldg(&x8[s0 * 8 + q]);
                acc_h8(aLo, aHi, v);
            }
            int deg = e - s;
            float invd = 1.0f / (float)(deg > 0 ? deg : 1);
            aLo.x *= invd; aLo.y *= invd; aLo.z *= invd; aLo.w *= invd;
            aHi.x *= invd; aHi.y *= invd; aHi.z *= invd; aHi.w *= invd;
            xv = __ldg(&x8[node * 8 + q]);
        }
        uint2 hLo = f4_to_h4(aLo);
        uint2 hHi = f4_to_h4(aHi);
        *(uint4*)&sA[n * AROW + q * 8] = make_uint4(hLo.x, hLo.y, hHi.x, hHi.y);
        *(uint4*)&sA[n * AROW + 64 + q * 8] = xv;
    }
    __syncthreads();

    // ---- wmma GEMM: C[32][64] = sA[32][128] @ whL[128][64], fp32 accumulate ----
    {
        int wid = tid >> 5;                 // 0..7
        int rowblk = wid >> 2;              // 0..1 (16 nodes each)
        int colblk = wid & 3;               // 0..3 (16 cols each)
        wmma::fragment<wmma::accumulator, 16, 16, 16, float> c0;
        wmma::fill_fragment(c0, 0.0f);
#pragma unroll
        for (int k = 0; k < 8; k++) {
            wmma::fragment<wmma::matrix_a, 16, 16, 16, __half, wmma::row_major> af;
            wmma::load_matrix_sync(af, sA + rowblk * 16 * AROW + k * 16, AROW);
            wmma::fragment<wmma::matrix_b, 16, 16, 16, __half, wmma::row_major> b0;
            wmma::load_matrix_sync(b0, whL + k * 16 * 64 + colblk * 16, 64);
            wmma::mma_sync(c0, af, b0, c0);
        }
        wmma::store_matrix_sync(sC + rowblk * 16 * CROW + colblk * 16, c0, CROW,
                                wmma::mem_row_major);
    }
    __syncthreads();

    // ---- epilogue: bias + relu (n = tid>>3, 8 features per thread) ----
    int n = tid >> 3;
    int f0 = (tid & 7) * 8;
    float4 y[2];
    {
        const float* cr = &sC[n * CROW + f0];
#pragma unroll
        for (int j = 0; j < 2; j++) {
            float4 v = *(const float4*)&cr[j * 4];
            float4 bb;
            bb.x = __ldg(&bl[f0 + j * 4]);     bb.y = __ldg(&bl[f0 + j * 4 + 1]);
            bb.z = __ldg(&bl[f0 + j * 4 + 2]); bb.w = __ldg(&bl[f0 + j * 4 + 3]);
            v.x = fmaxf(v.x + bb.x, 0.f); v.y = fmaxf(v.y + bb.y, 0.f);
            v.z = fmaxf(v.z + bb.z, 0.f); v.w = fmaxf(v.w + bb.w, 0.f);
            y[j] = v;
        }
    }
    int gn = node0 + n;
    if (!FINAL) {
        if (gn < N_NODES) {
            __half* dh = (__half*)dst;
            uint2 h0 = f4_to_h4(y[0]);
            uint2 h1 = f4_to_h4(y[1]);
            *(uint4*)&dh[gn * 64 + f0] = make_uint4(h0.x, h0.y, h1.x, h1.y);
        }
        __syncthreads();   // protect sA/sC before next tile
    } else {
        float* cr = &sC[n * CROW + f0];
        *(float4*)&cr[0] = y[0];
        *(float4*)&cr[4] = y[1];
        __syncthreads();
        // output projection: n2 = tid>>3 (0..31), o0 = (tid&7)*2 (2 outputs/thread)
        int n2 = tid >> 3;
        int o0 = (tid & 7) * 2;
        float o_a = __ldg(&bout[o0]);
        float o_b = __ldg(&bout[o0 + 1]);
        const float* yr = &sC[n2 * CROW];
#pragma unroll 4
        for (int k4 = 0; k4 < 16; k4++) {
            float4 yv = *(const float4*)&yr[k4 * 4];
#pragma unroll
            for (int kk = 0; kk < 4; kk++) {
                float s = (&yv.x)[kk];
                const float* wr = &Wog[(k4 * 4 + kk) * 16 + o0];
                o_a = fmaf(s, __ldg(&wr[0]), o_a);
                o_b = fmaf(s, __ldg(&wr[1]), o_b);
            }
        }
        int gn2 = node0 + n2;
        if (gn2 < N_NODES) {
            float2 ov = make_float2(o_a, o_b);
            *(float2*)&((float*)dst)[gn2 * OUT_DIM + o0] = ov;
        }
        __syncthreads();
    }
}

// ---------------- persistent kernel ----------------
__global__ void __launch_bounds__(TPB, 4) fused_kernel(
    const float* __restrict__ x, const int* __restrict__ ei,
    const float* __restrict__ Wl, const float* __restrict__ bl,
    const float* __restrict__ Wr, const float* __restrict__ Wout,
    const float* __restrict__ bout, float* __restrict__ out) {
    __shared__ __half sA[TILE_N * AROW];   // 8.5 KB
    __shared__ float sC[TILE_N * CROW];    // 8.5 KB
    __shared__ int sInts[8];

    int tid = threadIdx.x;
    int b = blockIdx.x;
    int gtid = b * TPB + tid;
    int lane = tid & 31, w = tid >> 5;

    // phase 0: zero counts + convert x and weights to fp16
    for (int i = gtid; i < N_NODES; i += GSTRIDE) g_count[i] = 0;
    {
        const float4* x4 = (const float4*)x;
        uint2* hx = (uint2*)g_hx;
        for (int i = gtid; i < N_NODES * HIDDEN / 4; i += GSTRIDE) {
            float4 v = __ldg(&x4[i]);
            hx[i] = f4_to_h4(v);
        }
        for (int i = gtid; i < 3 * 128 * 64; i += GSTRIDE) {
            int l = i / 8192;
            int r = i - l * 8192;
            int k = r >> 6;
            int f = r & 63;
            float v = (k < 64) ? __ldg(&Wl[l * 4096 + k * 64 + f])
                               : __ldg(&Wr[l * 4096 + (k - 64) * 64 + f]);
            g_wh[i] = __float2half_rn(v);
        }
    }
    grid_barrier();

    // phase 1: histogram
    {
        const int4* dst4 = (const int4*)(ei + N_EDGES);
        for (int t = gtid; t < N_EDGES / 4; t += GSTRIDE) {
            int4 d = __ldg(&dst4[t]);
            atomicAdd(&g_count[d.x], 1);
            atomicAdd(&g_count[d.y], 1);
            atomicAdd(&g_count[d.z], 1);
            atomicAdd(&g_count[d.w], 1);
        }
    }
    grid_barrier();

    // phase 2a: block-local exclusive scan of CHUNK counts
    {
        int base = b * CHUNK;
        int idx = base + tid;
        int v = (tid < CHUNK && idx < N_NODES) ? g_count[idx] : 0;
        int s = v;
#pragma unroll
        for (int d = 1; d < 32; d <<= 1) {
            int tv = __shfl_up_sync(0xffffffffu, s, d);
            if (lane >= d) s += tv;
        }
        if (lane == 31) sInts[w] = s;
        __syncthreads();
        if (tid == 0) {
            int acc = 0;
#pragma unroll
            for (int k = 0; k < 8; k++) { int t2 = sInts[k]; sInts[k] = acc; acc += t2; }
        }
        __syncthreads();
        int incl = s + sInts[w];
        if (tid < CHUNK && idx < N_NODES) g_off[idx] = incl - v;
        if (tid == TPB - 1) g_blocksum[b] = incl;
    }
    grid_barrier();

    // phase 2b: block 0 scans the NBLK block sums (3 per thread)
    if (b == 0) {
        int base2 = tid * 3;
        int v0 = (base2 + 0 < NBLK) ? g_blocksum[base2 + 0] : 0;
        int v1 = (base2 + 1 < NBLK) ? g_blocksum[base2 + 1] : 0;
        int v2 = (base2 + 2 < NBLK) ? g_blocksum[base2 + 2] : 0;
        int tsum = v0 + v1 + v2;
        int s = tsum;
#pragma unroll
        for (int d = 1; d < 32; d <<= 1) {
            int tv = __shfl_up_sync(0xffffffffu, s, d);
            if (lane >= d) s += tv;
        }
        if (lane == 31) sInts[w] = s;
        __syncthreads();
        if (tid == 0) {
            int acc = 0;
#pragma unroll
            for (int k = 0; k < 8; k++) { int t2 = sInts[k]; sInts[k] = acc; acc += t2; }
        }
        __syncthreads();
        int excl = (s - tsum) + sInts[w];
        if (base2 + 0 < NBLK) { g_blockoff[base2 + 0] = excl; excl += v0; }
        if (base2 + 1 < NBLK) { g_blockoff[base2 + 1] = excl; excl += v1; }
        if (base2 + 2 < NBLK) { g_blockoff[base2 + 2] = excl; excl += v2; }
    }
    grid_barrier();

    // phase 2c: add block offsets; init fill cursors
    {
        int off = g_blockoff[b];
        int idx = b * CHUNK + tid;
        if (tid < CHUNK && idx < N_NODES) {
            int o = g_off[idx] + off;
            g_off[idx] = o;
            g_count[idx] = o;
        }
        if (gtid == 0) g_off[N_NODES] = N_EDGES;
    }
    grid_barrier();

    // phase 3: fill CSR
    {
        const int4* src4 = (const int4*)ei;
        const int4* dst4 = (const int4*)(ei + N_EDGES);
        for (int t = gtid; t < N_EDGES / 4; t += GSTRIDE) {
            int4 sv = __ldg(&src4[t]);
            int4 d = __ldg(&dst4[t]);
            g_csr[atomicAdd(&g_count[d.x], 1)] = sv.x;
            g_csr[atomicAdd(&g_count[d.y], 1)] = sv.y;
            g_csr[atomicAdd(&g_count[d.z], 1)] = sv.z;
            g_csr[atomicAdd(&g_count[d.w], 1)] = sv.w;
        }
    }
    grid_barrier();

    // ---- layer 1: g_hx -> g_h0 ----
    for (int tile = b; tile < NTILES; tile += NBLK)
        layer_tile<false>(g_hx, g_wh, Wout, bl, bout, g_h0, tile, tid, sA, sC);
    grid_barrier();

    // ---- layer 2: g_h0 -> g_h1 ----
    for (int tile = b; tile < NTILES; tile += NBLK)
        layer_tile<false>(g_h0, g_wh + 8192, Wout, bl + HIDDEN, bout, g_h1,
                          tile, tid, sA, sC);
    grid_barrier();

    // ---- layer 3 + output projection: g_h1 -> out ----
    for (int tile = b; tile < NTILES; tile += NBLK)
        layer_tile<true>(g_h1, g_wh + 16384, Wout, bl + 2 * HIDDEN, bout, out,
                         tile, tid, sA, sC);
}

extern "C" void kernel_launch(void* const* d_in, const int* in_sizes, int n_in,
                              void* d_out, int out_size) {
    const float* x = (const float*)d_in[0];
    const int* ei = (const int*)d_in[1];
    const float* Wl = (const float*)d_in[2];
    const float* bl = (const float*)d_in[3];
    const float* Wr = (const float*)d_in[4];
    const float* Wout = (const float*)d_in[5];
    const float* bout = (const float*)d_in[6];
    float* out = (float*)d_out;

    fused_kernel<<<NBLK, TPB>>>(x, ei, Wl, bl, Wr, Wout, bout, out);
}

// round 17
// speedup vs baseline: 1.0836x; 1.0285x over previous
#include <cuda_runtime.h>
#include <cuda_fp16.h>
#include <mma.h>

using namespace nvcuda;

#define N_NODES 50000
#define N_EDGES 800000
#define HIDDEN 64
#define OUT_DIM 16
#define NBLK 592          // 4 blocks/SM x 148 SMs
#define TPB 256
#define GSTRIDE (NBLK * TPB)
#define CHUNK 85          // ceil(50000/592)
#define TILE_N 32
#define NTILES 1563       // ceil(50000/32)
#define AROW 136          // sA row stride in halves (128 + 8 pad)
#define CROW 68           // sC row stride in floats (64 + 4 pad)

// ---------------- device scratch ----------------
__device__ int g_count[N_NODES];
__device__ int g_off[N_NODES + 1];
__device__ int g_csr[N_EDGES];
__device__ int g_blocksum[NBLK];
__device__ int g_blockoff[NBLK];
__device__ unsigned g_bar_cnt;
__device__ unsigned g_bar_gen;
__device__ __align__(16) __half g_hx[N_NODES * HIDDEN];
__device__ __align__(16) __half g_h0[N_NODES * HIDDEN];
__device__ __align__(16) __half g_h1[N_NODES * HIDDEN];
__device__ __align__(16) __half g_wh[3 * 128 * 64];   // fp16 [layer][k][f]; k<64 Wl, k>=64 Wr

// ---------------- software grid barrier ----------------
__device__ __forceinline__ void grid_barrier() {
    __syncthreads();
    if (threadIdx.x == 0) {
        unsigned gen = *((volatile unsigned*)&g_bar_gen);
        __threadfence();
        unsigned a = atomicAdd(&g_bar_cnt, 1u);
        if (a == NBLK - 1) {
            g_bar_cnt = 0;
            __threadfence();
            atomicExch(&g_bar_gen, gen + 1u);
        } else {
            while (*((volatile unsigned*)&g_bar_gen) == gen) { __nanosleep(32); }
        }
        __threadfence();
    }
    __syncthreads();
}

__device__ __forceinline__ void acc_h8(float4& lo, float4& hi, uint4 v) {
    __half2* h = (__half2*)&v;
    float2 f0 = __half22float2(h[0]);
    float2 f1 = __half22float2(h[1]);
    float2 f2 = __half22float2(h[2]);
    float2 f3 = __half22float2(h[3]);
    lo.x += f0.x; lo.y += f0.y; lo.z += f1.x; lo.w += f1.y;
    hi.x += f2.x; hi.y += f2.y; hi.z += f3.x; hi.w += f3.y;
}
__device__ __forceinline__ uint2 f4_to_h4(float4 a) {
    __half2 lo = __floats2half2_rn(a.x, a.y);
    __half2 hi = __floats2half2_rn(a.z, a.w);
    uint2 r;
    r.x = *(unsigned*)&lo;
    r.y = *(unsigned*)&hi;
    return r;
}

// ---------------- one 32-node tile: fp16 gather -> wmma (weights in smem) ----------------
template <bool FINAL>
__device__ __forceinline__ void layer_tile(
    const __half* __restrict__ xin,
    const __half* sW,                // fp16 [128][64] staged in smem
    const float* __restrict__ Wog,   // [64][16] (FINAL)
    const float* __restrict__ bl,
    const float* __restrict__ bout,
    void* __restrict__ dst,
    int tile, int tid, __half* sA, float* sC) {
    int node0 = tile * TILE_N;
    // ---- gather: 8 threads/node, 32 nodes (R14/R16-proven loop) ----
    {
        int ln = tid >> 3, q = tid & 7;
        const uint4* x8 = (const uint4*)xin;
        int n = ln;
        int node = node0 + n;
        float4 aLo = make_float4(0.f, 0.f, 0.f, 0.f);
        float4 aHi = aLo;
        uint4 xv = make_uint4(0u, 0u, 0u, 0u);
        if (node < N_NODES) {
            int s = __ldg(&g_off[node]);
            int e = __ldg(&g_off[node + 1]);
            int i = s;
            int i0 = 0, i1 = 0, i2 = 0, i3 = 0;
            if (i + 4 <= e) {
                i0 = __ldg(&g_csr[i]);     i1 = __ldg(&g_csr[i + 1]);
                i2 = __ldg(&g_csr[i + 2]); i3 = __ldg(&g_csr[i + 3]);
            }
            while (i + 4 <= e) {
                uint4 v0 = __ldg(&x8[i0 * 8 + q]);
                uint4 v1 = __ldg(&x8[i1 * 8 + q]);
                uint4 v2 = __ldg(&x8[i2 * 8 + q]);
                uint4 v3 = __ldg(&x8[i3 * 8 + q]);
                i += 4;
                if (i + 4 <= e) {
                    i0 = __ldg(&g_csr[i]);     i1 = __ldg(&g_csr[i + 1]);
                    i2 = __ldg(&g_csr[i + 2]); i3 = __ldg(&g_csr[i + 3]);
                }
                acc_h8(aLo, aHi, v0); acc_h8(aLo, aHi, v1);
                acc_h8(aLo, aHi, v2); acc_h8(aLo, aHi, v3);
            }
            for (; i < e; i++) {
                int s0 = __ldg(&g_csr[i]);
                uint4 v = __ldg(&x8[s0 * 8 + q]);
                acc_h8(aLo, aHi, v);
            }
            int deg = e - s;
            float invd = 1.0f / (float)(deg > 0 ? deg : 1);
            aLo.x *= invd; aLo.y *= invd; aLo.z *= invd; aLo.w *= invd;
            aHi.x *= invd; aHi.y *= invd; aHi.z *= invd; aHi.w *= invd;
            xv = __ldg(&x8[node * 8 + q]);
        }
        uint2 hLo = f4_to_h4(aLo);
        uint2 hHi = f4_to_h4(aHi);
        *(uint4*)&sA[n * AROW + q * 8] = make_uint4(hLo.x, hLo.y, hHi.x, hHi.y);
        *(uint4*)&sA[n * AROW + 64 + q * 8] = xv;
    }
    __syncthreads();

    // ---- wmma GEMM: C[32][64] = sA[32][128] @ sW[128][64], fp32 accumulate ----
    {
        int wid = tid >> 5;                 // 0..7
        int rowblk = wid >> 2;              // 0..1
        int colblk = wid & 3;               // 0..3
        wmma::fragment<wmma::accumulator, 16, 16, 16, float> c0;
        wmma::fill_fragment(c0, 0.0f);
#pragma unroll
        for (int k = 0; k < 8; k++) {
            wmma::fragment<wmma::matrix_a, 16, 16, 16, __half, wmma::row_major> af;
            wmma::load_matrix_sync(af, sA + rowblk * 16 * AROW + k * 16, AROW);
            wmma::fragment<wmma::matrix_b, 16, 16, 16, __half, wmma::row_major> b0;
            wmma::load_matrix_sync(b0, sW + k * 16 * 64 + colblk * 16, 64);
            wmma::mma_sync(c0, af, b0, c0);
        }
        wmma::store_matrix_sync(sC + rowblk * 16 * CROW + colblk * 16, c0, CROW,
                                wmma::mem_row_major);
    }
    __syncthreads();

    // ---- epilogue: bias + relu ----
    int n = tid >> 3;
    int f0 = (tid & 7) * 8;
    float4 y[2];
    {
        const float* cr = &sC[n * CROW + f0];
#pragma unroll
        for (int j = 0; j < 2; j++) {
            float4 v = *(const float4*)&cr[j * 4];
            float4 bb;
            bb.x = __ldg(&bl[f0 + j * 4]);     bb.y = __ldg(&bl[f0 + j * 4 + 1]);
            bb.z = __ldg(&bl[f0 + j * 4 + 2]); bb.w = __ldg(&bl[f0 + j * 4 + 3]);
            v.x = fmaxf(v.x + bb.x, 0.f); v.y = fmaxf(v.y + bb.y, 0.f);
            v.z = fmaxf(v.z + bb.z, 0.f); v.w = fmaxf(v.w + bb.w, 0.f);
            y[j] = v;
        }
    }
    int gn = node0 + n;
    if (!FINAL) {
        if (gn < N_NODES) {
            __half* dh = (__half*)dst;
            uint2 h0 = f4_to_h4(y[0]);
            uint2 h1 = f4_to_h4(y[1]);
            *(uint4*)&dh[gn * 64 + f0] = make_uint4(h0.x, h0.y, h1.x, h1.y);
        }
        __syncthreads();
    } else {
        float* cr = &sC[n * CROW + f0];
        *(float4*)&cr[0] = y[0];
        *(float4*)&cr[4] = y[1];
        __syncthreads();
        int n2 = tid >> 3;
        int o0 = (tid & 7) * 2;
        float o_a = __ldg(&bout[o0]);
        float o_b = __ldg(&bout[o0 + 1]);
        const float* yr = &sC[n2 * CROW];
#pragma unroll 4
        for (int k4 = 0; k4 < 16; k4++) {
            float4 yv = *(const float4*)&yr[k4 * 4];
#pragma unroll
            for (int kk = 0; kk < 4; kk++) {
                float s = (&yv.x)[kk];
                const float* wr = &Wog[(k4 * 4 + kk) * 16 + o0];
                o_a = fmaf(s, __ldg(&wr[0]), o_a);
                o_b = fmaf(s, __ldg(&wr[1]), o_b);
            }
        }
        int gn2 = node0 + n2;
        if (gn2 < N_NODES) {
            float2 ov = make_float2(o_a, o_b);
            *(float2*)&((float*)dst)[gn2 * OUT_DIM + o0] = ov;
        }
        __syncthreads();
    }
}

// ---------------- persistent kernel ----------------
__global__ void __launch_bounds__(TPB, 4) fused_kernel(
    const float* __restrict__ x, const int* __restrict__ ei,
    const float* __restrict__ Wl, const float* __restrict__ bl,
    const float* __restrict__ Wr, const float* __restrict__ Wout,
    const float* __restrict__ bout, float* __restrict__ out) {
    __shared__ __half sA[TILE_N * AROW];   // 8.5 KB
    __shared__ float sC[TILE_N * CROW];    // 8.5 KB
    __shared__ __half sW[128 * 64];        // 16 KB — layer weights staged
    __shared__ int sInts[8];

    int tid = threadIdx.x;
    int b = blockIdx.x;
    int gtid = b * TPB + tid;
    int lane = tid & 31, w = tid >> 5;

    // phase 0: zero counts + convert x and weights to fp16
    for (int i = gtid; i < N_NODES; i += GSTRIDE) g_count[i] = 0;
    {
        const float4* x4 = (const float4*)x;
        uint2* hx = (uint2*)g_hx;
        for (int i = gtid; i < N_NODES * HIDDEN / 4; i += GSTRIDE) {
            float4 v = __ldg(&x4[i]);
            hx[i] = f4_to_h4(v);
        }
        for (int i = gtid; i < 3 * 128 * 64; i += GSTRIDE) {
            int l = i / 8192;
            int r = i - l * 8192;
            int k = r >> 6;
            int f = r & 63;
            float v = (k < 64) ? __ldg(&Wl[l * 4096 + k * 64 + f])
                               : __ldg(&Wr[l * 4096 + (k - 64) * 64 + f]);
            g_wh[i] = __float2half_rn(v);
        }
    }
    grid_barrier();

    // phase 1: histogram
    {
        const int4* dst4 = (const int4*)(ei + N_EDGES);
        for (int t = gtid; t < N_EDGES / 4; t += GSTRIDE) {
            int4 d = __ldg(&dst4[t]);
            atomicAdd(&g_count[d.x], 1);
            atomicAdd(&g_count[d.y], 1);
            atomicAdd(&g_count[d.z], 1);
            atomicAdd(&g_count[d.w], 1);
        }
    }
    grid_barrier();

    // phase 2a: block-local exclusive scan of CHUNK counts
    {
        int base = b * CHUNK;
        int idx = base + tid;
        int v = (tid < CHUNK && idx < N_NODES) ? g_count[idx] : 0;
        int s = v;
#pragma unroll
        for (int d = 1; d < 32; d <<= 1) {
            int tv = __shfl_up_sync(0xffffffffu, s, d);
            if (lane >= d) s += tv;
        }
        if (lane == 31) sInts[w] = s;
        __syncthreads();
        if (tid == 0) {
            int acc = 0;
#pragma unroll
            for (int k = 0; k < 8; k++) { int t2 = sInts[k]; sInts[k] = acc; acc += t2; }
        }
        __syncthreads();
        int incl = s + sInts[w];
        if (tid < CHUNK && idx < N_NODES) g_off[idx] = incl - v;
        if (tid == TPB - 1) g_blocksum[b] = incl;
    }
    grid_barrier();

    // phase 2b: block 0 scans the NBLK block sums (3 per thread)
    if (b == 0) {
        int base2 = tid * 3;
        int v0 = (base2 + 0 < NBLK) ? g_blocksum[base2 + 0] : 0;
        int v1 = (base2 + 1 < NBLK) ? g_blocksum[base2 + 1] : 0;
        int v2 = (base2 + 2 < NBLK) ? g_blocksum[base2 + 2] : 0;
        int tsum = v0 + v1 + v2;
        int s = tsum;
#pragma unroll
        for (int d = 1; d < 32; d <<= 1) {
            int tv = __shfl_up_sync(0xffffffffu, s, d);
            if (lane >= d) s += tv;
        }
        if (lane == 31) sInts[w] = s;
        __syncthreads();
        if (tid == 0) {
            int acc = 0;
#pragma unroll
            for (int k = 0; k < 8; k++) { int t2 = sInts[k]; sInts[k] = acc; acc += t2; }
        }
        __syncthreads();
        int excl = (s - tsum) + sInts[w];
        if (base2 + 0 < NBLK) { g_blockoff[base2 + 0] = excl; excl += v0; }
        if (base2 + 1 < NBLK) { g_blockoff[base2 + 1] = excl; excl += v1; }
        if (base2 + 2 < NBLK) { g_blockoff[base2 + 2] = excl; excl += v2; }
    }
    grid_barrier();

    // phase 2c: add block offsets; init fill cursors
    {
        int off = g_blockoff[b];
        int idx = b * CHUNK + tid;
        if (tid < CHUNK && idx < N_NODES) {
            int o = g_off[idx] + off;
            g_off[idx] = o;
            g_count[idx] = o;
        }
        if (gtid == 0) g_off[N_NODES] = N_EDGES;
    }
    grid_barrier();

    // phase 3: fill CSR
    {
        const int4* src4 = (const int4*)ei;
        const int4* dst4 = (const int4*)(ei + N_EDGES);
        for (int t = gtid; t < N_EDGES / 4; t += GSTRIDE) {
            int4 sv = __ldg(&src4[t]);
            int4 d = __ldg(&dst4[t]);
            g_csr[atomicAdd(&g_count[d.x], 1)] = sv.x;
            g_csr[atomicAdd(&g_count[d.y], 1)] = sv.y;
            g_csr[atomicAdd(&g_count[d.z], 1)] = sv.z;
            g_csr[atomicAdd(&g_count[d.w], 1)] = sv.w;
        }
    }
    grid_barrier();

    // ---- layer 1: g_hx -> g_h0 ----
    {
        const uint4* wsrc = (const uint4*)g_wh;
        uint4* wdst = (uint4*)sW;
        for (int i = tid; i < 1024; i += TPB) wdst[i] = __ldg(&wsrc[i]);
        __syncthreads();
        for (int tile = b; tile < NTILES; tile += NBLK)
            layer_tile<false>(g_hx, sW, Wout, bl, bout, g_h0, tile, tid, sA, sC);
    }
    grid_barrier();

    // ---- layer 2: g_h0 -> g_h1 ----
    {
        const uint4* wsrc = (const uint4*)(g_wh + 8192);
        uint4* wdst = (uint4*)sW;
        for (int i = tid; i < 1024; i += TPB) wdst[i] = __ldg(&wsrc[i]);
        __syncthreads();
        for (int tile = b; tile < NTILES; tile += NBLK)
            layer_tile<false>(g_h0, sW, Wout, bl + HIDDEN, bout, g_h1, tile, tid, sA, sC);
    }
    grid_barrier();

    // ---- layer 3 + output projection: g_h1 -> out ----
    {
        const uint4* wsrc = (const uint4*)(g_wh + 16384);
        uint4* wdst = (uint4*)sW;
        for (int i = tid; i < 1024; i += TPB) wdst[i] = __ldg(&wsrc[i]);
        __syncthreads();
        for (int tile = b; tile < NTILES; tile += NBLK)
            layer_tile<true>(g_h1, sW, Wout, bl + 2 * HIDDEN, bout, out, tile, tid, sA, sC);
    }
}

extern "C" void kernel_launch(void* const* d_in, const int* in_sizes, int n_in,
                              void* d_out, int out_size) {
    const float* x = (const float*)d_in[0];
    const int* ei = (const int*)d_in[1];
    const float* Wl = (const float*)d_in[2];
    const float* bl = (const float*)d_in[3];
    const float* Wr = (const float*)d_in[4];
    const float* Wout = (const float*)d_in[5];
    const float* bout = (const float*)d_in[6];
    float* out = (float*)d_out;

    fused_kernel<<<NBLK, TPB>>>(x, ei, Wl, bl, Wr, Wout, bout, out);
}